// round 1
// baseline (speedup 1.0000x reference)
#include <cuda_runtime.h>

// Exact algebraic reduction of the reference:
//   adder2d(x,W) = -sum|...| <= 0 elementwise  =>  relu(adder2d(x,W1)) == 0 identically.
//   adder2d(0,W2)[b,o,h,w] = -sum_{c,kh,kw} |W2[o,c,kh,kw]|   (padding contributes 0 patches too)
//   out = x - 0.1 * S[o],  S[o] = sum |W2[o,:,:,:]|
//
// Input layout (metadata order): d_in[0]=x [8,64,64,64] f32, d_in[1]=W1, d_in[2]=W2 [64,64,3,3] f32.
// Output: [8,64,64,64] f32.

__device__ float g_S[64];  // holds -0.1 * sum|W2[o]|

static constexpr int CKK = 64 * 3 * 3;   // 576 floats per output channel of W2
static constexpr int N_ELEM = 8 * 64 * 64 * 64;   // 2,097,152
static constexpr int N_F4 = N_ELEM / 4;           // 524,288

// Kernel 1: per-o L1 norm of W2. 256 threads: 4 threads per o, each sums 36 float4.
__global__ void compute_s_kernel(const float* __restrict__ W2) {
    __shared__ float partial[256];
    const int t = threadIdx.x;
    const int o = t >> 2;       // 0..63
    const int part = t & 3;     // 0..3
    // W2 + o*576 is 16B-aligned (576*4 = 2304 = 144*16)
    const float4* w4 = reinterpret_cast<const float4*>(W2 + o * CKK) + part * 36;
    float s0 = 0.f, s1 = 0.f;
#pragma unroll
    for (int i = 0; i < 36; i += 2) {
        float4 a = w4[i];
        float4 b = w4[i + 1];
        s0 += fabsf(a.x) + fabsf(a.y) + fabsf(a.z) + fabsf(a.w);
        s1 += fabsf(b.x) + fabsf(b.y) + fabsf(b.z) + fabsf(b.w);
    }
    partial[t] = s0 + s1;
    __syncthreads();
    if (part == 0) {
        float s = partial[t] + partial[t + 1] + partial[t + 2] + partial[t + 3];
        g_S[o] = -0.1f * s;
    }
}

// Kernel 2: out[i] = x[i] + g_S[o], o warp-uniform per float4 index block of 1024.
__global__ void residual_kernel(const float4* __restrict__ x4, float4* __restrict__ out4) {
    int i = blockIdx.x * blockDim.x + threadIdx.x;
    if (i >= N_F4) return;
    // Element layout [B,O,H,W]: each (b,o) slab is 4096 floats = 1024 float4.
    const float b = __ldg(&g_S[(i >> 10) & 63]);
    float4 v = x4[i];
    v.x += b; v.y += b; v.z += b; v.w += b;
    out4[i] = v;
}

extern "C" void kernel_launch(void* const* d_in, const int* in_sizes, int n_in,
                              void* d_out, int out_size) {
    const float* x  = (const float*)d_in[0];
    const float* W2 = (const float*)d_in[2];
    float* out = (float*)d_out;

    compute_s_kernel<<<1, 256>>>(W2);

    const int threads = 256;
    const int blocks = N_F4 / threads;   // 2048
    residual_kernel<<<blocks, threads>>>(
        reinterpret_cast<const float4*>(x), reinterpret_cast<float4*>(out));
}

// round 3
// speedup vs baseline: 1.7830x; 1.7830x over previous
#include <cuda_runtime.h>

// Exact algebraic reduction of the reference (verified R1, rel_err 6.5e-8):
//   adder2d(x,W) = -sum|.| <= 0  =>  relu(adder2d(x,W1)) == 0 identically
//   adder2d(0,W2)[b,o,h,w] = -sum_{c,kh,kw}|W2[o,c,kh,kw]|
//   out = x - 0.1 * S[o],  S[o] = sum |W2[o,:,:,:]|
//
// R3 == R2 resubmit (R2 bench was an infra failure, theory untested):
// single fused kernel; each block serves half of one (b,o) slab (512 float4),
// recomputes its own S[o] from W2 (L2-resident; 2.4 MB total redundant reads),
// streams out = x + bias with 2 float4/thread. Cross-warp combine via shared
// array instead of atomicAdd (removes ATOMS serialization from the prologue).
//
// Inputs: d_in[0]=x [8,64,64,64] f32, d_in[1]=W1 (unused), d_in[2]=W2 [64,64,3,3] f32.

static constexpr int CKK   = 64 * 3 * 3;              // 576
static constexpr int N_F4  = (8 * 64 * 64 * 64) / 4;  // 524288
static constexpr int F4_PER_BLOCK = 512;              // half a (b,o) slab
static constexpr int BLOCKS = N_F4 / F4_PER_BLOCK;    // 1024

__global__ void __launch_bounds__(256) fused_residual_kernel(
    const float4* __restrict__ x4,
    const float*  __restrict__ W2,
    float4* __restrict__ out4)
{
    const int t    = threadIdx.x;
    const int base = blockIdx.x * F4_PER_BLOCK;
    const int o    = (blockIdx.x >> 1) & 63;   // slab index = blockIdx>>1, 64 o-channels

    // Issue the streaming loads FIRST (independent regs; W2 work hides under them).
    float4 v0 = x4[base + t];
    float4 v1 = x4[base + 256 + t];

    // Per-block S[o] = sum |W2[o, :]| over 576 floats: 256 threads, strided.
    const float* w = W2 + o * CKK;
    float s = fabsf(w[t]) + fabsf(w[t + 256]);
    if (t < CKK - 512) s += fabsf(w[t + 512]);     // t < 64

    // Warp butterfly reduce.
#pragma unroll
    for (int d = 16; d; d >>= 1)
        s += __shfl_xor_sync(0xFFFFFFFFu, s, d);

    // Cross-warp combine: 8 shared slots, every thread sums all 8 (no atomics,
    // no second barrier; the 8-way sum is 7 FADDs on broadcast LDS reads).
    __shared__ float warp_s[8];
    if ((t & 31) == 0) warp_s[t >> 5] = s;
    __syncthreads();
    float tot = warp_s[0] + warp_s[1] + warp_s[2] + warp_s[3]
              + warp_s[4] + warp_s[5] + warp_s[6] + warp_s[7];
    const float bias = -0.1f * tot;

    v0.x += bias; v0.y += bias; v0.z += bias; v0.w += bias;
    v1.x += bias; v1.y += bias; v1.z += bias; v1.w += bias;
    out4[base + t]       = v0;
    out4[base + 256 + t] = v1;
}

extern "C" void kernel_launch(void* const* d_in, const int* in_sizes, int n_in,
                              void* d_out, int out_size) {
    const float* x  = (const float*)d_in[0];
    const float* W2 = (const float*)d_in[2];
    fused_residual_kernel<<<BLOCKS, 256>>>(
        reinterpret_cast<const float4*>(x), W2,
        reinterpret_cast<float4*>(d_out));
}

// round 5
// speedup vs baseline: 1.8621x; 1.0443x over previous
#include <cuda_runtime.h>

// Exact algebraic reduction of the reference (verified R1/R3, rel_err ~7e-8):
//   relu(adder2d(x,W1)) == 0 identically  =>  out = x - 0.1 * S[o],
//   S[o] = sum |W2[o,:,:,:]|  (576 floats per o)
//
// R5 == R4 resubmit (R4 bench was an infra failure, theory untested):
// warp-autonomous version. No shared memory, no __syncthreads.
// Each warp redundantly computes its own S[o] (6 loads/lane + 5 shfl),
// so the store path never waits on other warps. 4 front-batched float4
// x-loads per thread for MLP. 1024 blocks x 128 threads; block = half a
// (b,o) slab (512 float4); o = (blockIdx>>1) & 63.
//
// Inputs: d_in[0]=x [8,64,64,64] f32, d_in[1]=W1 (unused), d_in[2]=W2 [64,64,3,3] f32.

static constexpr int CKK  = 64 * 3 * 3;               // 576
static constexpr int N_F4 = (8 * 64 * 64 * 64) / 4;   // 524288
static constexpr int F4_PER_BLOCK = 512;
static constexpr int BLOCKS = N_F4 / F4_PER_BLOCK;    // 1024
static constexpr int THREADS = 128;

__global__ void __launch_bounds__(THREADS) fused_residual_kernel(
    const float4* __restrict__ x4,
    const float*  __restrict__ W2,
    float4* __restrict__ out4)
{
    const int t    = threadIdx.x;
    const int base = blockIdx.x * F4_PER_BLOCK;
    const int o    = (blockIdx.x >> 1) & 63;
    const int lane = t & 31;

    // Front-batch 4 independent streaming loads (MLP_p1 = 4).
    float4 v0 = x4[base + t];
    float4 v1 = x4[base + t + 128];
    float4 v2 = x4[base + t + 256];
    float4 v3 = x4[base + t + 384];

    // Per-WARP S[o]: 576 floats = 128 float4 (4/lane) + 64 scalars (2/lane).
    // These loads issue right behind the x-loads; L2-hot after wave 1.
    const float*  w  = W2 + o * CKK;            // 16B-aligned (2304 % 16 == 0)
    const float4* w4 = reinterpret_cast<const float4*>(w);
    float4 a0 = w4[lane];
    float4 a1 = w4[lane + 32];
    float4 a2 = w4[lane + 64];
    float4 a3 = w4[lane + 96];
    float  b0 = w[512 + lane];
    float  b1 = w[544 + lane];

    float s = fabsf(a0.x) + fabsf(a0.y) + fabsf(a0.z) + fabsf(a0.w)
            + fabsf(a1.x) + fabsf(a1.y) + fabsf(a1.z) + fabsf(a1.w)
            + fabsf(a2.x) + fabsf(a2.y) + fabsf(a2.z) + fabsf(a2.w)
            + fabsf(a3.x) + fabsf(a3.y) + fabsf(a3.z) + fabsf(a3.w)
            + fabsf(b0) + fabsf(b1);

#pragma unroll
    for (int d = 16; d; d >>= 1)
        s += __shfl_xor_sync(0xFFFFFFFFu, s, d);

    const float bias = -0.1f * s;

    v0.x += bias; v0.y += bias; v0.z += bias; v0.w += bias;
    v1.x += bias; v1.y += bias; v1.z += bias; v1.w += bias;
    v2.x += bias; v2.y += bias; v2.z += bias; v2.w += bias;
    v3.x += bias; v3.y += bias; v3.z += bias; v3.w += bias;

    out4[base + t]       = v0;
    out4[base + t + 128] = v1;
    out4[base + t + 256] = v2;
    out4[base + t + 384] = v3;
}

extern "C" void kernel_launch(void* const* d_in, const int* in_sizes, int n_in,
                              void* d_out, int out_size) {
    const float* x  = (const float*)d_in[0];
    const float* W2 = (const float*)d_in[2];
    fused_residual_kernel<<<BLOCKS, THREADS>>>(
        reinterpret_cast<const float4*>(x), W2,
        reinterpret_cast<float4*>(d_out));
}